// round 9
// baseline (speedup 1.0000x reference)
#include <cuda_runtime.h>
#include <cuda_fp16.h>
#include <cstdint>

#define N 8192
#define D 128
#define G 8                   // column stripes
#define MT 64                 // rows per CTA
#define NTILE 128             // cols per tile
#define NTILES 8              // tiles per CTA
#define KEEP 5                // slots kept per (row, stripe); each slot = 4 cols
#define STRH 136              // smem tile row stride in halfs (272B)
#define TBYTES 34816          // 128*136*2

// dynamic smem layout (bytes)
#define SM_SQ    0            // 2 * 128 floats = 1024
#define SM_A     1024         // 64*272 = 17408
#define SM_B     18432        // 2 * 34816 = 69632
#define SM_SCR   1024         // scratch over A after frag preload
#define SM_TOTAL 88064

__device__ __half   g_xh[N * D];
__device__ float    g_sq[N];              // ||x_j||^2 + 512
__device__ uint32_t g_topK[N * G * KEEP]; // slot keys (d2' bits | id7)
__device__ int      g_topJ[N * G * KEEP]; // slot base col index
__device__ float    g_partial[1024];
__device__ unsigned g_cnt = 0;

__device__ __forceinline__ bool better(float d1, int i1, float d2, int i2) {
    return (d1 < d2) || (d1 == d2 && i1 < i2);
}
__device__ __forceinline__ uint32_t smem_u32(const void* p) {
    uint32_t a;
    asm("{ .reg .u64 t; cvta.to.shared.u64 t, %1; cvt.u32.u64 %0, t; }" : "=r"(a) : "l"(p));
    return a;
}
__device__ __forceinline__ void ldsm_x4(uint32_t* r, uint32_t addr) {
    asm volatile("ldmatrix.sync.aligned.m8n8.x4.shared.b16 {%0,%1,%2,%3}, [%4];"
                 : "=r"(r[0]), "=r"(r[1]), "=r"(r[2]), "=r"(r[3]) : "r"(addr));
}
__device__ __forceinline__ void mma16816(float* d, const uint32_t* a, uint32_t b0, uint32_t b1) {
    asm volatile("mma.sync.aligned.m16n8k16.row.col.f32.f16.f16.f32 "
                 "{%0,%1,%2,%3}, {%4,%5,%6,%7}, {%8,%9}, {%0,%1,%2,%3};"
                 : "+f"(d[0]), "+f"(d[1]), "+f"(d[2]), "+f"(d[3])
                 : "r"(a[0]), "r"(a[1]), "r"(a[2]), "r"(a[3]), "r"(b0), "r"(b1));
}
__device__ __forceinline__ void cp_async16(uint32_t dst, const void* src) {
    asm volatile("cp.async.cg.shared.global [%0], [%1], 16;" :: "r"(dst), "l"(src));
}
__device__ __forceinline__ void cp_commit() { asm volatile("cp.async.commit_group;" ::: "memory"); }
__device__ __forceinline__ void cp_wait1() { asm volatile("cp.async.wait_group 1;" ::: "memory"); }
__device__ __forceinline__ void cp_wait0() { asm volatile("cp.async.wait_group 0;" ::: "memory"); }

// branchless depth-4 sorted insert on uint keys
__device__ __forceinline__ void ins4(uint32_t c, uint32_t* t) {
#pragma unroll
    for (int s = 0; s < 4; s++) {
        uint32_t lo = min(t[s], c);
        c = max(t[s], c);
        t[s] = lo;
    }
}
// branchless insert into sorted-5 list
__device__ __forceinline__ void ins5(uint32_t c, uint32_t* t) {
#pragma unroll
    for (int s = 0; s < 5; s++) {
        uint32_t lo = min(t[s], c);
        c = max(t[s], c);
        t[s] = lo;
    }
}

// ---------------------------------------------------------------------------
// Kernel P: fp16 cast + (row norm + 512)
// ---------------------------------------------------------------------------
__global__ void prep_kernel(const float* __restrict__ x) {
    int row  = blockIdx.x * 8 + (threadIdx.x >> 5);
    int lane = threadIdx.x & 31;
    const float* xr = x + row * D;
    float s = 0.f;
#pragma unroll
    for (int kk = 0; kk < 4; kk++) {
        int k = lane + 32 * kk;
        float v = xr[k];
        g_xh[row * D + k] = __float2half_rn(v);
        s = fmaf(v, v, s);
    }
#pragma unroll
    for (int o = 16; o; o >>= 1) s += __shfl_xor_sync(0xffffffffu, s, o);
    if (lane == 0) g_sq[row] = s + 512.0f;
}

// ---------------------------------------------------------------------------
// Kernel B: approx fp16 Gram + quad-slot keyed selection.
// Grid (G, 128), 256 threads = 8 warps: wr = w>>1 (16-row group), wc = w&1
// (64-col group). Slot = 4 cols {0,1,8,9}+base; key = bits(min d2') | id7
// (id7 = u<<4 | t<<2 | lane2). Lossless: finalize rescores all 4 slot cols.
// ---------------------------------------------------------------------------
__global__ __launch_bounds__(256, 2) void gram_top_kernel() {
    extern __shared__ char sm[];
    float* sqc = (float*)(sm + SM_SQ);
    const uint32_t smBase = smem_u32(sm);
    const uint32_t smA = smBase + SM_A;
    const uint32_t smB = smBase + SM_B;

    const int tid = threadIdx.x;
    const int w = tid >> 5, l = tid & 31;
    const int wr = w >> 1, wc = w & 1;
    const int lane2 = l & 3;
    const int bx = blockIdx.x;
    const int rowBase = blockIdx.y * MT;

    // prologue: issue B(0) first (overlaps A smem fill)
    {
#pragma unroll
        for (int v = 0; v < 8; v++) {
            int i = tid + v * 256;
            int col = i >> 4, k8 = i & 15;
            cp_async16(smB + (uint32_t)(col * (STRH * 2) + k8 * 16),
                       g_xh + (bx * NTILE + col) * D + k8 * 8);
        }
        cp_commit();
        if (tid < 128) sqc[tid] = g_sq[bx * NTILE + tid];
    }

    // A tile to smem
    {
        const __half* Ag = g_xh + rowBase * D;
#pragma unroll
        for (int v = 0; v < 4; v++) {
            int i = tid + v * 256;
            int r = i >> 4, c8 = i & 15;
            uint4 val = *(const uint4*)(Ag + r * D + c8 * 8);
            *(uint4*)(sm + SM_A + r * (STRH * 2) + c8 * 16) = val;
        }
    }
    __syncthreads();

    // A fragments register-resident for all 8 k-steps
    const uint32_t aBase = smA + (uint32_t)((wr * 16 + (l & 15)) * (STRH * 2)) + ((l >> 4) & 1) * 16;
    uint32_t af[8][4];
#pragma unroll
    for (int ks = 0; ks < 8; ks++) ldsm_x4(af[ks], aBase + ks * 32);

    uint32_t kd[2][4];
#pragma unroll
    for (int h = 0; h < 2; h++)
#pragma unroll
        for (int s = 0; s < 4; s++) kd[h][s] = 0xFFFFFFFFu;

    const uint32_t bOff = (uint32_t)((wc * 64 + (l & 7) + ((l >> 4) & 1) * 8) * (STRH * 2)) + ((l >> 3) & 1) * 16;

    float rsq = 0.f;
    for (int u = 0; u < NTILES; u++) {
        if (u < NTILES - 1) {
            const int cb1 = (bx + (u + 1) * G) * NTILE;
            const uint32_t dstB = smB + (uint32_t)(((u + 1) & 1) * TBYTES);
#pragma unroll
            for (int v = 0; v < 8; v++) {
                int i = tid + v * 256;
                int col = i >> 4, k8 = i & 15;
                cp_async16(dstB + (uint32_t)(col * (STRH * 2) + k8 * 16),
                           g_xh + (cb1 + col) * D + k8 * 8);
            }
            cp_commit();
            if (tid < 128) rsq = g_sq[cb1 + tid];
            cp_wait1();
        } else {
            cp_wait0();
        }
        __syncthreads();

        float acc[8][4];
#pragma unroll
        for (int nf = 0; nf < 8; nf++)
#pragma unroll
            for (int q = 0; q < 4; q++) acc[nf][q] = 0.f;

        const uint32_t bBase = smB + (uint32_t)((u & 1) * TBYTES) + bOff;
#pragma unroll
        for (int ks = 0; ks < 8; ks++) {
            uint32_t b[4][4];
#pragma unroll
            for (int nf4 = 0; nf4 < 4; nf4++)
                ldsm_x4(b[nf4], bBase + nf4 * 16 * (STRH * 2) + ks * 32);
#pragma unroll
            for (int nf = 0; nf < 8; nf++)
                mma16816(acc[nf], af[ks], b[nf >> 1][(nf & 1) * 2], b[nf >> 1][(nf & 1) * 2 + 1]);
        }

        // quad-slot epilogue: slot = cols {base, base+1, base+8, base+9}
        const float* sq1 = sqc + (u & 1) * 128;
#pragma unroll
        for (int t = 0; t < 4; t++) {
            float2 sjA = *(const float2*)&sq1[wc * 64 + t * 16 + lane2 * 2];
            float2 sjB = *(const float2*)&sq1[wc * 64 + t * 16 + 8 + lane2 * 2];
            const uint32_t idb = (uint32_t)((u << 4) | (t << 2) | lane2);
#pragma unroll
            for (int h = 0; h < 2; h++) {
                float k0 = fmaf(-2.f, acc[2 * t][h * 2 + 0], sjA.x);
                float k1 = fmaf(-2.f, acc[2 * t][h * 2 + 1], sjA.y);
                float k2 = fmaf(-2.f, acc[2 * t + 1][h * 2 + 0], sjB.x);
                float k3 = fmaf(-2.f, acc[2 * t + 1][h * 2 + 1], sjB.y);
                float m = fminf(fminf(k0, k1), fminf(k2, k3));
                uint32_t key = (__float_as_uint(m) & 0xFFFFFF80u) | idb;
                ins4(key, kd[h]);
            }
        }

        if (u < NTILES - 1 && tid < 128) sqc[((u + 1) & 1) * 128 + tid] = rsq;
        __syncthreads();
    }

    // merge across the 4 lanes of each quad
    uint32_t t5[2][KEEP];
#pragma unroll
    for (int h = 0; h < 2; h++) {
#pragma unroll
        for (int s = 0; s < 4; s++) t5[h][s] = kd[h][s];
        t5[h][4] = 0xFFFFFFFFu;
#pragma unroll
        for (int s = 0; s < 4; s++)
            ins5(__shfl_xor_sync(0xffffffffu, kd[h][s], 1), t5[h]);
        uint32_t o[KEEP];
#pragma unroll
        for (int s = 0; s < KEEP; s++) o[s] = __shfl_xor_sync(0xffffffffu, t5[h][s], 2);
#pragma unroll
        for (int s = 0; s < KEEP; s++) ins5(o[s], t5[h]);
    }

    // cross-wc merge: wc==1 publishes keys, wc==0 decodes + merges + writes
    uint32_t* scr = (uint32_t*)(sm + SM_SCR);
    __syncthreads();
    if (wc == 1 && lane2 == 0) {
#pragma unroll
        for (int h = 0; h < 2; h++) {
            int rl = wr * 16 + (l >> 2) + h * 8;
#pragma unroll
            for (int s = 0; s < KEEP; s++) scr[rl * KEEP + s] = t5[h][s];
        }
    }
    __syncthreads();
    if (wc == 0 && lane2 == 0) {
#pragma unroll
        for (int h = 0; h < 2; h++) {
            int rl = wr * 16 + (l >> 2) + h * 8;
            uint32_t rk[KEEP]; int rj[KEEP];
#pragma unroll
            for (int s = 0; s < KEEP; s++) {
                uint32_t id = t5[h][s] & 0x7Fu;
                rk[s] = t5[h][s];
                rj[s] = bx * 128 + (int)(id >> 4) * (G * NTILE) +
                        (int)((id >> 2) & 3) * 16 + (int)(id & 3) * 2;
            }
#pragma unroll
            for (int e = 0; e < KEEP; e++) {
                uint32_t ck = scr[rl * KEEP + e];
                uint32_t id = ck & 0x7Fu;
                int cj = bx * 128 + (int)(id >> 4) * (G * NTILE) + 64 +
                         (int)((id >> 2) & 3) * 16 + (int)(id & 3) * 2;
#pragma unroll
                for (int s = 0; s < KEEP; s++) {
                    bool lt = ck < rk[s];
                    uint32_t nk = lt ? ck : rk[s];
                    int      nj = lt ? cj : rj[s];
                    ck = lt ? rk[s] : ck;
                    cj = lt ? rj[s] : cj;
                    rk[s] = nk; rj[s] = nj;
                }
            }
            int row = rowBase + rl;
#pragma unroll
            for (int s = 0; s < KEEP; s++) {
                g_topK[(row * G + bx) * KEEP + s] = rk[s];
                g_topJ[(row * G + bx) * KEEP + s] = rj[s];
            }
        }
    }
}

// ---------------------------------------------------------------------------
// Kernel C: threshold-select slots by key, exact fp32 rescoring of their
// cols -> true 5th NN -> hinge, fused deterministic mean.
// ---------------------------------------------------------------------------
__global__ void finalize_kernel(const float* __restrict__ x, const float* __restrict__ p,
                                float* __restrict__ out) {
    __shared__ int   sj[8][24];
    __shared__ float shw[8];
    __shared__ float shr[256];
    __shared__ bool  amLast;
    int w    = threadIdx.x >> 5;
    int lane = threadIdx.x & 31;
    int row  = blockIdx.x * 8 + w;

    const uint32_t* kp = g_topK + row * (G * KEEP);
    const int*      jp = g_topJ + row * (G * KEEP);
    uint32_t k0 = kp[lane];
    int      j0 = jp[lane];
    uint32_t k1 = 0xFFFFFFFFu;
    int      j1 = 0;
    if (lane < 8) { k1 = kp[32 + lane]; j1 = jp[32 + lane]; }

    // 5 extraction rounds -> 5th-smallest slot key (duplicate-removal biases
    // upward only: safe)
    uint32_t a0 = k0, a1 = k1, gm = 0;
#pragma unroll
    for (int r = 0; r < 5; r++) {
        uint32_t mv = min(a0, a1);
#pragma unroll
        for (int o = 16; o; o >>= 1) mv = min(mv, __shfl_xor_sync(0xffffffffu, mv, o));
        gm = mv;
        if (a0 == gm) a0 = 0xFFFFFFFFu;
        if (a1 == gm) a1 = 0xFFFFFFFFu;
    }
    float vthr = __uint_as_float(gm & 0xFFFFFF80u) + 4.0f;

    bool p0 = __uint_as_float(k0 & 0xFFFFFF80u) <= vthr;
    bool p1 = (lane < 8) && (__uint_as_float(k1 & 0xFFFFFF80u) <= vthr);
    uint32_t b0 = __ballot_sync(0xffffffffu, p0);
    uint32_t b1 = __ballot_sync(0xffffffffu, p1);
    uint32_t ltm = (lane == 31) ? 0x7FFFFFFFu : ((1u << lane) - 1u);
    int c0 = __popc(b0);
    if (p0) { int pos = __popc(b0 & ltm);      if (pos < 24) sj[w][pos] = j0; }
    if (p1) { int pos = c0 + __popc(b1 & ltm); if (pos < 24) sj[w][pos] = j1; }
    int m = min(c0 + __popc(b1), 24);
    __syncwarp();

    float4 xi = ((const float4*)(x + row * D))[lane];

    float t5d[5]; int t5i[5];
#pragma unroll
    for (int s = 0; s < 5; s++) { t5d[s] = __int_as_float(0x7f800000); t5i[s] = 0x7fffffff; }

    for (int s = 0; s < m; s++) {
        int jb = sj[w][s];
#pragma unroll
        for (int e = 0; e < 4; e++) {
            int j = jb + (e & 1) + (e >> 1) * 8;   // 0,1,8,9
            float4 xj = ((const float4*)(x + j * D))[lane];
            float d0 = xi.x - xj.x, d1 = xi.y - xj.y, d2_ = xi.z - xj.z, d3 = xi.w - xj.w;
            float sv = fmaf(d0, d0, fmaf(d1, d1, fmaf(d2_, d2_, d3 * d3)));
#pragma unroll
            for (int o = 16; o; o >>= 1) sv += __shfl_xor_sync(0xffffffffu, sv, o);
            float d2 = fmaxf(sv, 1e-12f);
            if (better(d2, j, t5d[4], t5i[4])) {
                float cd = d2; int ci = j;
#pragma unroll
                for (int k = 0; k < 5; k++) {
                    if (better(cd, ci, t5d[k], t5i[k])) {
                        float td = t5d[k]; t5d[k] = cd; cd = td;
                        int   ti = t5i[k]; t5i[k] = ci; ci = ti;
                    }
                }
            }
        }
    }
    int neg = t5i[4];

    float4 pi = ((const float4*)(p + row * D))[lane];
    float4 xn = ((const float4*)(x + neg * D))[lane];
    float ap0 = xi.x - pi.x + 1e-6f, ap1 = xi.y - pi.y + 1e-6f;
    float ap2 = xi.z - pi.z + 1e-6f, ap3 = xi.w - pi.w + 1e-6f;
    float an0 = xi.x - xn.x + 1e-6f, an1 = xi.y - xn.y + 1e-6f;
    float an2 = xi.z - xn.z + 1e-6f, an3 = xi.w - xn.w + 1e-6f;
    float sap = fmaf(ap0, ap0, fmaf(ap1, ap1, fmaf(ap2, ap2, ap3 * ap3)));
    float san = fmaf(an0, an0, fmaf(an1, an1, fmaf(an2, an2, an3 * an3)));
#pragma unroll
    for (int o = 16; o; o >>= 1) {
        sap += __shfl_xor_sync(0xffffffffu, sap, o);
        san += __shfl_xor_sync(0xffffffffu, san, o);
    }
    if (lane == 0)
        shw[w] = fmaxf(sqrtf(sap) - sqrtf(san) + 0.3f, 0.f);
    __syncthreads();

    if (threadIdx.x == 0) {
        float s = 0.f;
#pragma unroll
        for (int i = 0; i < 8; i++) s += shw[i];
        g_partial[blockIdx.x] = s;
    }
    __threadfence();
    if (threadIdx.x == 0)
        amLast = (atomicInc(&g_cnt, 1023u) == 1023u);
    __syncthreads();

    if (amLast) {
        float s = 0.f;
        for (int i = threadIdx.x; i < 1024; i += 256) s += g_partial[i];
        shr[threadIdx.x] = s;
        __syncthreads();
        for (int o = 128; o; o >>= 1) {
            if (threadIdx.x < o) shr[threadIdx.x] += shr[threadIdx.x + o];
            __syncthreads();
        }
        if (threadIdx.x == 0) out[0] = shr[0] * (1.0f / N);
    }
}

// ---------------------------------------------------------------------------
extern "C" void kernel_launch(void* const* d_in, const int* in_sizes, int n_in,
                              void* d_out, int out_size) {
    const float* x   = (const float*)d_in[0];
    const float* pos = (const float*)d_in[1];
    float* out = (float*)d_out;

    cudaFuncSetAttribute(gram_top_kernel,
                         cudaFuncAttributeMaxDynamicSharedMemorySize, SM_TOTAL);

    prep_kernel<<<N / 8, 256>>>(x);
    gram_top_kernel<<<dim3(G, N / MT), 256, SM_TOTAL>>>();
    finalize_kernel<<<N / 8, 256>>>(x, pos, out);
}

// round 11
// speedup vs baseline: 1.4117x; 1.4117x over previous
#include <cuda_runtime.h>
#include <cuda_fp16.h>
#include <cstdint>

#define N 8192
#define D 128
#define NB 64                 // 64 blocks of 128 rows/cols
#define NTRI 2080             // NB*(NB+1)/2 tiles
#define STRB 272              // smem tile row stride bytes (136 halfs)

// dynamic smem layout (bytes)
#define SM_A     0            // 128*272 = 34816
#define SM_B     34816        // 34816
#define SM_SQR   69632        // 128 floats (row block norms+512)
#define SM_SQC   70144        // 128 floats (col block norms+512)
#define SM_P2    70656        // phase-2 col merge: 128*3 uints = 1536
#define SM_TOTAL 73728
#define SM_CSCR  0            // col scratch overlays A: 128*65*4 = 33280

__device__ __half   g_xh[N * D];
__device__ float    g_sq[N];            // ||x||^2 + 512
__device__ uint32_t g_keys[N][NB][3];   // per (row, block): top-3 slot keys
__device__ float    g_partial[1024];
__device__ unsigned g_cnt = 0;

__device__ __forceinline__ bool better(float d1, int i1, float d2, int i2) {
    return (d1 < d2) || (d1 == d2 && i1 < i2);
}
__device__ __forceinline__ uint32_t smem_u32(const void* p) {
    uint32_t a;
    asm("{ .reg .u64 t; cvta.to.shared.u64 t, %1; cvt.u32.u64 %0, t; }" : "=r"(a) : "l"(p));
    return a;
}
__device__ __forceinline__ void ldsm_x4(uint32_t* r, uint32_t addr) {
    asm volatile("ldmatrix.sync.aligned.m8n8.x4.shared.b16 {%0,%1,%2,%3}, [%4];"
                 : "=r"(r[0]), "=r"(r[1]), "=r"(r[2]), "=r"(r[3]) : "r"(addr));
}
__device__ __forceinline__ void mma16816(float* d, const uint32_t* a, uint32_t b0, uint32_t b1) {
    asm volatile("mma.sync.aligned.m16n8k16.row.col.f32.f16.f16.f32 "
                 "{%0,%1,%2,%3}, {%4,%5,%6,%7}, {%8,%9}, {%0,%1,%2,%3};"
                 : "+f"(d[0]), "+f"(d[1]), "+f"(d[2]), "+f"(d[3])
                 : "r"(a[0]), "r"(a[1]), "r"(a[2]), "r"(a[3]), "r"(b0), "r"(b1));
}
__device__ __forceinline__ void cp_async16(uint32_t dst, const void* src) {
    asm volatile("cp.async.cg.shared.global [%0], [%1], 16;" :: "r"(dst), "l"(src));
}
__device__ __forceinline__ void cp_commit() { asm volatile("cp.async.commit_group;" ::: "memory"); }
__device__ __forceinline__ void cp_wait0() { asm volatile("cp.async.wait_group 0;" ::: "memory"); }

// branchless depth-3 sorted insert on uint keys (6 ops)
__device__ __forceinline__ void ins3(uint32_t c, uint32_t* t) {
#pragma unroll
    for (int s = 0; s < 3; s++) {
        uint32_t lo = min(t[s], c);
        c = max(t[s], c);
        t[s] = lo;
    }
}

// ---------------------------------------------------------------------------
// Kernel P: fp16 cast + (row norm + 512)
// ---------------------------------------------------------------------------
__global__ void prep_kernel(const float* __restrict__ x) {
    int row  = blockIdx.x * 8 + (threadIdx.x >> 5);
    int lane = threadIdx.x & 31;
    const float* xr = x + row * D;
    float s = 0.f;
#pragma unroll
    for (int kk = 0; kk < 4; kk++) {
        int k = lane + 32 * kk;
        float v = xr[k];
        g_xh[row * D + k] = __float2half_rn(v);
        s = fmaf(v, v, s);
    }
#pragma unroll
    for (int o = 16; o; o >>= 1) s += __shfl_xor_sync(0xffffffffu, s, o);
    if (lane == 0) g_sq[row] = s + 512.0f;
}

// ---------------------------------------------------------------------------
// Kernel B: triangular fp16 Gram tiles (I<=J), dual-side slot selection.
// 2080 CTAs x 256 threads (8 warps, each 16 rows x 128 cols).
// Row-side: per row, top-3 quad-slots (4 cols each) -> g_keys[row][J].
// Col-side (I<J): per col, top-3 pair-slots (2 rows each) -> g_keys[col][I].
// Key = bits(sq_partner + 512 - 2*dot) truncated | id7.
// ---------------------------------------------------------------------------
__global__ __launch_bounds__(256, 2) void gram_top_kernel() {
    extern __shared__ char sm[];
    const uint32_t smBase = smem_u32(sm);
    float* sqR_sm = (float*)(sm + SM_SQR);
    float* sqC_sm = (float*)(sm + SM_SQC);

    const int tid = threadIdx.x;
    const int w = tid >> 5, l = tid & 31;
    const int lane2 = l & 3;

    // triangular tile index -> (I, J)
    int t = blockIdx.x, I = 0;
    while (t >= NB - I) { t -= NB - I; I++; }
    const int J = I + t;

    // load A (rows block I) and B (cols block J): 128 rows x 256 B each
    {
        const __half* Ag = g_xh + I * 128 * D;
        const __half* Bg = g_xh + J * 128 * D;
#pragma unroll
        for (int v = 0; v < 8; v++) {
            int i = tid + v * 256;            // 2048 16B chunks each
            int r = i >> 4, c16 = i & 15;
            cp_async16(smBase + SM_A + (uint32_t)(r * STRB + c16 * 16), Ag + r * D + c16 * 8);
            cp_async16(smBase + SM_B + (uint32_t)(r * STRB + c16 * 16), Bg + r * D + c16 * 8);
        }
        cp_commit();
        if (tid < 128) sqR_sm[tid] = g_sq[I * 128 + tid];
        else           sqC_sm[tid - 128] = g_sq[J * 128 + tid - 128];
        cp_wait0();
    }
    __syncthreads();

    // MMA: 16 rows x 128 cols per warp
    const uint32_t aBase = smBase + SM_A + (uint32_t)((w * 16 + (l & 15)) * STRB) + ((l >> 4) & 1) * 16;
    const uint32_t bBase = smBase + SM_B + (uint32_t)(((l & 7) + ((l >> 4) & 1) * 8) * STRB) + ((l >> 3) & 1) * 16;

    float acc[16][4];
#pragma unroll
    for (int nf = 0; nf < 16; nf++)
#pragma unroll
        for (int q = 0; q < 4; q++) acc[nf][q] = 0.f;

#pragma unroll
    for (int ks = 0; ks < 8; ks++) {
        uint32_t a[4];
        ldsm_x4(a, aBase + ks * 32);
#pragma unroll
        for (int nf4 = 0; nf4 < 8; nf4++) {
            uint32_t b[4];
            ldsm_x4(b, bBase + (uint32_t)(nf4 * 16 * STRB) + ks * 32);
            mma16816(acc[nf4 * 2],     a, b[0], b[1]);
            mma16816(acc[nf4 * 2 + 1], a, b[2], b[3]);
        }
    }

    const float sqRh0 = sqR_sm[w * 16 + (l >> 2)];
    const float sqRh1 = sqR_sm[w * 16 + (l >> 2) + 8];

    // ---- row-side: quad-slots {base, +1, +8, +9}, base = t8*16 + lane2*2 ----
    uint32_t kd[2][3];
#pragma unroll
    for (int h = 0; h < 2; h++)
#pragma unroll
        for (int s = 0; s < 3; s++) kd[h][s] = 0xFFFFFFFFu;

#pragma unroll
    for (int t8 = 0; t8 < 8; t8++) {
        float2 sjA = *(const float2*)&sqC_sm[t8 * 16 + lane2 * 2];
        float2 sjB = *(const float2*)&sqC_sm[t8 * 16 + 8 + lane2 * 2];
        const uint32_t idb = (uint32_t)((t8 << 2) | lane2);
#pragma unroll
        for (int h = 0; h < 2; h++) {
            float k0 = fmaf(-2.f, acc[2 * t8][h * 2 + 0], sjA.x);
            float k1 = fmaf(-2.f, acc[2 * t8][h * 2 + 1], sjA.y);
            float k2 = fmaf(-2.f, acc[2 * t8 + 1][h * 2 + 0], sjB.x);
            float k3 = fmaf(-2.f, acc[2 * t8 + 1][h * 2 + 1], sjB.y);
            float m = fminf(fminf(k0, k1), fminf(k2, k3));
            ins3((__float_as_uint(m) & 0xFFFFFF80u) | idb, kd[h]);
        }
    }
    // merge over the 4 lanes of each quad (rows identical within quad)
#pragma unroll
    for (int h = 0; h < 2; h++) {
#pragma unroll
        for (int off = 1; off < 4; off <<= 1) {
            uint32_t o[3];
#pragma unroll
            for (int s = 0; s < 3; s++) o[s] = __shfl_xor_sync(0xffffffffu, kd[h][s], off);
#pragma unroll
            for (int s = 0; s < 3; s++) ins3(o[s], kd[h]);
        }
    }
    if (lane2 == 0) {
#pragma unroll
        for (int h = 0; h < 2; h++) {
            int row = I * 128 + w * 16 + (l >> 2) + h * 8;
#pragma unroll
            for (int s = 0; s < 3; s++) g_keys[row][J][s] = kd[h][s];
        }
    }

    // ---- col-side (I < J): pair-slots {r, r+8} over rows ----
    if (I < J) {
        __syncthreads();   // all ldsm reads of A done; overlay scratch
        uint32_t* cscr = (uint32_t*)(sm + SM_CSCR);   // [128 cols][65] (padded)
        const uint32_t cid = (uint32_t)((w << 3) | (l >> 2));   // 6-bit slot id
#pragma unroll
        for (int nf = 0; nf < 16; nf++)
#pragma unroll
            for (int q = 0; q < 2; q++) {
                int c = nf * 8 + lane2 * 2 + q;
                float kk = fminf(fmaf(-2.f, acc[nf][q],     sqRh0),
                                 fmaf(-2.f, acc[nf][2 + q], sqRh1));
                cscr[c * 65 + cid] = (__float_as_uint(kk) & 0xFFFFFF80u) | cid;
            }
        __syncthreads();

        // phase 2: two threads per col, each reduces 32 of the 64 keys
        int c = tid & 127, half = tid >> 7;
        uint32_t t3[3] = {0xFFFFFFFFu, 0xFFFFFFFFu, 0xFFFFFFFFu};
#pragma unroll
        for (int k = 0; k < 32; k++) ins3(cscr[c * 65 + half * 32 + k], t3);
        uint32_t* p2 = (uint32_t*)(sm + SM_P2);
        if (half == 1) {
#pragma unroll
            for (int s = 0; s < 3; s++) p2[c * 3 + s] = t3[s];
        }
        __syncthreads();
        if (half == 0) {
#pragma unroll
            for (int s = 0; s < 3; s++) ins3(p2[c * 3 + s], t3);
            int col = J * 128 + c;
#pragma unroll
            for (int s = 0; s < 3; s++) g_keys[col][I][s] = t3[s];
        }
    }
}

// ---------------------------------------------------------------------------
// Kernel C: per-row 5th-smallest slot key over 192 keys, threshold-select,
// exact fp32 rescore of slot members -> true 5th NN -> hinge, fused mean.
// ---------------------------------------------------------------------------
__global__ void finalize_kernel(const float* __restrict__ x, const float* __restrict__ p,
                                float* __restrict__ out) {
    __shared__ int   sj[8][24];
    __shared__ float shw[8];
    __shared__ float shr[256];
    __shared__ bool  amLast;
    int w    = threadIdx.x >> 5;
    int lane = threadIdx.x & 31;
    int row  = blockIdx.x * 8 + w;
    int Jr   = row >> 7;

    const uint32_t* kp = &g_keys[row][0][0];   // 192 keys
    uint32_t k[6];
#pragma unroll
    for (int v = 0; v < 6; v++) k[v] = kp[lane + 32 * v];

    // 5 extraction rounds -> 5th-smallest slot key (dupe removal biases up: safe)
    uint32_t a[6], gm = 0;
#pragma unroll
    for (int v = 0; v < 6; v++) a[v] = k[v];
#pragma unroll
    for (int r = 0; r < 5; r++) {
        uint32_t mv = a[0];
#pragma unroll
        for (int v = 1; v < 6; v++) mv = min(mv, a[v]);
#pragma unroll
        for (int o = 16; o; o >>= 1) mv = min(mv, __shfl_xor_sync(0xffffffffu, mv, o));
        gm = mv;
#pragma unroll
        for (int v = 0; v < 6; v++) if (a[v] == gm) a[v] = 0xFFFFFFFFu;
    }
    float thr = __uint_as_float(gm & 0xFFFFFF80u) + 1.0f;

    // compact passing slots into smem (decode to member base + side flag)
    int cnt = 0;
#pragma unroll
    for (int v = 0; v < 6; v++) {
        bool pass = __uint_as_float(k[v] & 0xFFFFFF80u) <= thr;
        uint32_t bal = __ballot_sync(0xffffffffu, pass);
        if (pass) {
            int pos = cnt + __popc(bal & ((1u << lane) - 1u));
            if (pos < 24) {
                int kpos = lane + 32 * v;
                int b = kpos / 3;                 // block index
                uint32_t id = k[v] & 0x7Fu;
                int e;
                if (b >= Jr)  // row-side quad slot
                    e = (b * 128 + (int)((id >> 2) & 7) * 16 + (int)(id & 3) * 2) | 0x40000000;
                else          // col-side pair slot
                    e = b * 128 + (int)((id >> 3) & 7) * 16 + (int)(id & 7);
                sj[w][pos] = e;
            }
        }
        cnt += __popc(bal);
    }
    int m = min(cnt, 24);
    __syncwarp();

    float4 xi = ((const float4*)(x + row * D))[lane];

    float t5d[5]; int t5i[5];
#pragma unroll
    for (int s = 0; s < 5; s++) { t5d[s] = __int_as_float(0x7f800000); t5i[s] = 0x7fffffff; }

    for (int s = 0; s < m; s++) {
        int e = sj[w][s];
        bool quad = (e & 0x40000000) != 0;
        int base = e & 0x3FFFFFFF;
        int ne = quad ? 4 : 2;
        for (int i4 = 0; i4 < ne; i4++) {
            int j = quad ? (base + (i4 & 1) + (i4 >> 1) * 8)   // {0,1,8,9}
                         : (base + i4 * 8);                    // {0,8}
            float4 xj = ((const float4*)(x + j * D))[lane];
            float d0 = xi.x - xj.x, d1 = xi.y - xj.y, d2_ = xi.z - xj.z, d3 = xi.w - xj.w;
            float sv = fmaf(d0, d0, fmaf(d1, d1, fmaf(d2_, d2_, d3 * d3)));
#pragma unroll
            for (int o = 16; o; o >>= 1) sv += __shfl_xor_sync(0xffffffffu, sv, o);
            float d2 = fmaxf(sv, 1e-12f);
            if (better(d2, j, t5d[4], t5i[4])) {
                float cd = d2; int ci = j;
#pragma unroll
                for (int kk = 0; kk < 5; kk++) {
                    if (better(cd, ci, t5d[kk], t5i[kk])) {
                        float td = t5d[kk]; t5d[kk] = cd; cd = td;
                        int   ti = t5i[kk]; t5i[kk] = ci; ci = ti;
                    }
                }
            }
        }
    }
    int neg = t5i[4];

    float4 pi = ((const float4*)(p + row * D))[lane];
    float4 xn = ((const float4*)(x + neg * D))[lane];
    float ap0 = xi.x - pi.x + 1e-6f, ap1 = xi.y - pi.y + 1e-6f;
    float ap2 = xi.z - pi.z + 1e-6f, ap3 = xi.w - pi.w + 1e-6f;
    float an0 = xi.x - xn.x + 1e-6f, an1 = xi.y - xn.y + 1e-6f;
    float an2 = xi.z - xn.z + 1e-6f, an3 = xi.w - xn.w + 1e-6f;
    float sap = fmaf(ap0, ap0, fmaf(ap1, ap1, fmaf(ap2, ap2, ap3 * ap3)));
    float san = fmaf(an0, an0, fmaf(an1, an1, fmaf(an2, an2, an3 * an3)));
#pragma unroll
    for (int o = 16; o; o >>= 1) {
        sap += __shfl_xor_sync(0xffffffffu, sap, o);
        san += __shfl_xor_sync(0xffffffffu, san, o);
    }
    if (lane == 0)
        shw[w] = fmaxf(sqrtf(sap) - sqrtf(san) + 0.3f, 0.f);
    __syncthreads();

    if (threadIdx.x == 0) {
        float s = 0.f;
#pragma unroll
        for (int i = 0; i < 8; i++) s += shw[i];
        g_partial[blockIdx.x] = s;
    }
    __threadfence();
    if (threadIdx.x == 0)
        amLast = (atomicInc(&g_cnt, 1023u) == 1023u);
    __syncthreads();

    if (amLast) {
        float s = 0.f;
        for (int i = threadIdx.x; i < 1024; i += 256) s += g_partial[i];
        shr[threadIdx.x] = s;
        __syncthreads();
        for (int o = 128; o; o >>= 1) {
            if (threadIdx.x < o) shr[threadIdx.x] += shr[threadIdx.x + o];
            __syncthreads();
        }
        if (threadIdx.x == 0) out[0] = shr[0] * (1.0f / N);
    }
}

// ---------------------------------------------------------------------------
extern "C" void kernel_launch(void* const* d_in, const int* in_sizes, int n_in,
                              void* d_out, int out_size) {
    const float* x   = (const float*)d_in[0];
    const float* pos = (const float*)d_in[1];
    float* out = (float*)d_out;

    cudaFuncSetAttribute(gram_top_kernel,
                         cudaFuncAttributeMaxDynamicSharedMemorySize, SM_TOTAL);

    prep_kernel<<<N / 8, 256>>>(x);
    gram_top_kernel<<<NTRI, 256, SM_TOTAL>>>();
    finalize_kernel<<<N / 8, 256>>>(x, pos, out);
}